// round 17
// baseline (speedup 1.0000x reference)
#include <cuda_runtime.h>
#include <cuda_fp16.h>
#include <cstdint>

#define BATCH 2
#define LEN   256

__device__ uint32_t g_Wh[256*32];      // QKVG weights fp16x2  [out 256][in pairs 32]

__device__ __forceinline__ float ex2(float x) {
    float r; asm("ex2.approx.f32 %0, %1;" : "=f"(r) : "f"(x)); return r;
}
__device__ __forceinline__ uint32_t h16x2(float hi, float lo) {
    uint32_t r; asm("cvt.rn.f16x2.f32 %0, %1, %2;" : "=r"(r) : "f"(hi), "f"(lo)); return r;
}
__device__ __forceinline__ void mma_f16(float* c, const uint32_t* a, const uint32_t* b) {
    asm("mma.sync.aligned.m16n8k16.row.col.f32.f16.f16.f32 "
        "{%0,%1,%2,%3},{%4,%5,%6,%7},{%8,%9},{%0,%1,%2,%3};"
        : "+f"(c[0]), "+f"(c[1]), "+f"(c[2]), "+f"(c[3])
        : "r"(a[0]), "r"(a[1]), "r"(a[2]), "r"(a[3]), "r"(b[0]), "r"(b[1]));
}
#define LDSM4(r, addr) \
    asm volatile("ldmatrix.sync.aligned.m8n8.x4.shared.b16 {%0,%1,%2,%3}, [%4];" \
        : "=r"((r)[0]), "=r"((r)[1]), "=r"((r)[2]), "=r"((r)[3]) : "r"(addr))
#define LDSM4T(r, addr) \
    asm volatile("ldmatrix.sync.aligned.m8n8.x4.trans.shared.b16 {%0,%1,%2,%3}, [%4];" \
        : "=r"((r)[0]), "=r"((r)[1]), "=r"((r)[2]), "=r"((r)[3]) : "r"(addr))

// ---------------------------------------------------------------------------
// Kernel 0: one-time weight pack (QKVG -> fp16x2).
// ---------------------------------------------------------------------------
__global__ void __launch_bounds__(256) k_prep(
    const float* __restrict__ Wq, const float* __restrict__ Wk,
    const float* __restrict__ Wv, const float* __restrict__ Wg)
{
    const int idx = blockIdx.x * 256 + threadIdx.x;   // 0..8191
    const int m = idx >> 11, o = (idx >> 5) & 63, i2 = idx & 31;
    const float* W = (m == 0) ? Wq : (m == 1) ? Wk : (m == 2) ? Wv : Wg;
    float2 wv = *(const float2*)(W + o*64 + i2*2);
    g_Wh[idx] = h16x2(wv.y, wv.x);
}

// ---------------------------------------------------------------------------
// Fused kernel with per-head pipelined projection:
//   upfront: Q, gate, K/V head0 -> barrier
//   pass h:  project K/V head h+1 (disjoint smem cols), attention pass for
//            head h (16 kb), pack A[h], barrier -> publishes head h+1.
// Projection mma/LDSM issues inside the attention pass's MUFU bubbles.
// Math order per head unchanged -> bit-identical to R16.
// SMEM: sA[256][36w] | sK | sV | sWh[256][36] | sWo[64][36]
// ---------------------------------------------------------------------------
#define SM_K   36864
#define SM_V   73728
#define SM_WH  110592
#define SM_WO  147456
#define SMEMT  156672
#define QSCALE 0.3606737602222409f   /* 0.25 * log2(e) */

__global__ void __launch_bounds__(512, 1) k_fused(
    const float* __restrict__ z, const float* __restrict__ ln_scale,
    const float* __restrict__ ln_bias, const float* __restrict__ bg,
    const float* __restrict__ Wo, const float* __restrict__ bo,
    float* __restrict__ y)
{
    extern __shared__ char sm[];
    uint32_t* sA  = (uint32_t*)sm;               // zn fp16 [256][36w]
    uint32_t* sKp = (uint32_t*)(sm + SM_K);
    uint32_t* sVp = (uint32_t*)(sm + SM_V);
    uint32_t* sWh = (uint32_t*)(sm + SM_WH);
    uint32_t* sWo = (uint32_t*)(sm + SM_WO);
    uint32_t sb;
    asm("{ .reg .u64 t; cvta.to.shared.u64 t, %1; cvt.u32.u64 %0, t; }"
        : "=r"(sb) : "l"(sm));

    const int tid  = threadIdx.x;
    const int base = blockIdx.x * 256;           // global row base (b*L+l)*256

    // ---- stage weights ----
    for (int idx = tid; idx < 8192; idx += 512) {
        int O = idx >> 5, i2 = idx & 31;
        sWh[O*36 + i2] = g_Wh[idx];
    }
    for (int idx = tid; idx < 2048; idx += 512) {
        int n = idx >> 5, i2 = idx & 31;
        float2 wv = *(const float2*)(Wo + n*64 + i2*2);
        sWo[n*36 + i2] = h16x2(wv.y, wv.x);
    }

    // ---- LayerNorm: 2 threads per row (32 channels each) -> sA fp16 ----
    {
        const int r = tid >> 1, q = tid & 1;
        const float* zr = z + (size_t)(base + r)*64 + q*32;
        float4 zv[8];
        #pragma unroll
        for (int f = 0; f < 8; f++) zv[f] = ((const float4*)zr)[f];
        float s = 0.f, ss = 0.f;
        #pragma unroll
        for (int f = 0; f < 8; f++) {
            s  += zv[f].x + zv[f].y + zv[f].z + zv[f].w;
            ss += zv[f].x*zv[f].x + zv[f].y*zv[f].y
                + zv[f].z*zv[f].z + zv[f].w*zv[f].w;
        }
        s  += __shfl_xor_sync(0xffffffffu, s, 1);
        ss += __shfl_xor_sync(0xffffffffu, ss, 1);
        float mu  = s * (1.0f/64.0f);
        float var = ss * (1.0f/64.0f) - mu*mu;
        float rs  = rsqrtf(var + 1e-5f);
        #pragma unroll
        for (int f = 0; f < 8; f++) {
            float4 sc = ((const float4*)(ln_scale + q*32))[f];
            float4 bi = ((const float4*)(ln_bias  + q*32))[f];
            float v0 = (zv[f].x - mu)*rs*sc.x + bi.x;
            float v1 = (zv[f].y - mu)*rs*sc.y + bi.y;
            float v2 = (zv[f].z - mu)*rs*sc.z + bi.z;
            float v3 = (zv[f].w - mu)*rs*sc.w + bi.w;
            sA[r*36 + q*16 + f*2]     = h16x2(v1, v0);
            sA[r*36 + q*16 + f*2 + 1] = h16x2(v3, v2);
        }
    }
    __syncthreads();

    const int w = tid >> 5, lane = tid & 31;
    const int g = lane >> 2, t = lane & 3;
    const int lr = w*16 + g;                     // local rows lr, lr+8
    const int r0 = base + lr;                    // global rows
    const uint32_t frow = (lane & 15);           // ldmatrix row-lane
    const uint32_t fcol = (lane >> 4) << 4;      // +16B for second 8-ch group

    // ---- A fragments (persist across all projection steps) ----
    uint32_t af[4][4];
    {
        const int arow = w*16 + frow;
        #pragma unroll
        for (int kt = 0; kt < 4; kt++)
            LDSM4(af[kt], sb + arow*144 + kt*32 + fcol);
    }

    uint32_t qa[4][4];    // QK A-frags per head (prescaled)
    uint32_t Gh[4][4];    // gate frags per head (fp16)

// one projection j-pair: JP constant -> dispatch folds at compile time
#define PROJ_JP(JP) do {                                                      \
    float acc_[2][4] = {};                                                    \
    const uint32_t wb_ = ((JP)*16 + frow)*144 + fcol;                         \
    _Pragma("unroll")                                                         \
    for (int kt = 0; kt < 4; kt++) {                                          \
        uint32_t wh_[4];                                                      \
        LDSM4(wh_, sb + SM_WH + wb_ + kt*32);                                 \
        uint32_t b0_[2] = {wh_[0], wh_[2]}, b1_[2] = {wh_[1], wh_[3]};        \
        mma_f16(acc_[0], af[kt], b0_);                                        \
        mma_f16(acc_[1], af[kt], b1_);                                        \
    }                                                                         \
    _Pragma("unroll")                                                         \
    for (int jj = 0; jj < 2; jj++) {                                          \
        const int j_ = (JP)*2 + jj;                                           \
        if (j_ < 8) {                                                         \
            const int h_ = j_ >> 1, part_ = j_ & 1;                           \
            qa[h_][part_*2]   = h16x2(QSCALE*acc_[jj][1], QSCALE*acc_[jj][0]);\
            qa[h_][part_*2+1] = h16x2(QSCALE*acc_[jj][3], QSCALE*acc_[jj][2]);\
        } else if (j_ < 16) {                                                 \
            const int jx_ = j_ - 8;                                           \
            sKp[lr*36 + jx_*4 + t]     = h16x2(acc_[jj][1], acc_[jj][0]);     \
            sKp[(lr+8)*36 + jx_*4 + t] = h16x2(acc_[jj][3], acc_[jj][2]);     \
        } else if (j_ < 24) {                                                 \
            const int jx_ = j_ - 16;                                          \
            sVp[lr*36 + jx_*4 + t]     = h16x2(acc_[jj][1], acc_[jj][0]);     \
            sVp[(lr+8)*36 + jx_*4 + t] = h16x2(acc_[jj][3], acc_[jj][2]);     \
        } else {                                                              \
            const int jx_ = j_ - 24, h_ = jx_ >> 1, part_ = jx_ & 1;          \
            float2 bg2_ = *(const float2*)(bg + jx_*8 + 2*t);                 \
            float g0_ = 1.0f/(1.0f + ex2(-1.4426950408889634f*(acc_[jj][0] + bg2_.x))); \
            float g1_ = 1.0f/(1.0f + ex2(-1.4426950408889634f*(acc_[jj][1] + bg2_.y))); \
            float g2_ = 1.0f/(1.0f + ex2(-1.4426950408889634f*(acc_[jj][2] + bg2_.x))); \
            float g3_ = 1.0f/(1.0f + ex2(-1.4426950408889634f*(acc_[jj][3] + bg2_.y))); \
            Gh[h_][part_*2]   = h16x2(g1_, g0_);                              \
            Gh[h_][part_*2+1] = h16x2(g3_, g2_);                              \
        }                                                                     \
    }                                                                         \
} while (0)

    // ---- upfront: Q (jp0-3), gate (jp12-15), K head0 (jp4), V head0 (jp8) ----
    PROJ_JP(0);  PROJ_JP(1);  PROJ_JP(2);  PROJ_JP(3);
    PROJ_JP(12); PROJ_JP(13); PROJ_JP(14); PROJ_JP(15);
    PROJ_JP(4);  PROJ_JP(8);
    __syncthreads();

    // ---- per-head passes: project K/V h+1, attend head h ----
    uint32_t A[4][4];
    const uint32_t bones[2] = {0x3C003C00u, 0x3C003C00u};
    const uint32_t vbase = sb + SM_V + frow*144 + fcol;
    const int krow0 = g*36 + t;

    #pragma unroll
    for (int h = 0; h < 4; h++) {
        if (h == 0)      { PROJ_JP(5); PROJ_JP(9);  }   // K/V head 1
        else if (h == 1) { PROJ_JP(6); PROJ_JP(10); }   // K/V head 2
        else if (h == 2) { PROJ_JP(7); PROJ_JP(11); }   // K/V head 3

        float o0[4] = {0.f,0.f,0.f,0.f};
        float o1[4] = {0.f,0.f,0.f,0.f};
        float la[4] = {0.f,0.f,0.f,0.f};

        #pragma unroll
        for (int kb = 0; kb < 16; kb++) {
            uint32_t kf0[2], kf1[2];
            {
                const uint32_t* kp = sKp + (kb*16)*36 + krow0 + h*8;
                kf0[0] = kp[0];        kf0[1] = kp[4];
                kf1[0] = kp[8*36];     kf1[1] = kp[8*36 + 4];
            }
            uint32_t vf[4];
            LDSM4T(vf, vbase + kb*2304 + h*32);

            float s0[4] = {0.f,0.f,0.f,0.f}, s1[4] = {0.f,0.f,0.f,0.f};
            mma_f16(s0, qa[h], kf0);
            mma_f16(s1, qa[h], kf1);
            s0[0] = ex2(s0[0]); s0[1] = ex2(s0[1]);
            s0[2] = ex2(s0[2]); s0[3] = ex2(s0[3]);
            s1[0] = ex2(s1[0]); s1[1] = ex2(s1[1]);
            s1[2] = ex2(s1[2]); s1[3] = ex2(s1[3]);
            uint32_t pa[4];
            pa[0] = h16x2(s0[1], s0[0]);
            pa[1] = h16x2(s0[3], s0[2]);
            pa[2] = h16x2(s1[1], s1[0]);
            pa[3] = h16x2(s1[3], s1[2]);
            mma_f16(la, pa, bones);             // fp32 row-sum accumulator
            mma_f16(o0, pa, vf + 0);
            mma_f16(o1, pa, vf + 2);
        }

        // normalize + gate -> packed epilogue A fragments for head h
        {
            const float inv0 = 1.0f / la[0];    // row g
            const float inv1 = 1.0f / la[2];    // row g+8
            float2 G0a = __half22float2(*(__half2*)&Gh[h][0]);
            float2 G1a = __half22float2(*(__half2*)&Gh[h][1]);
            float2 G0b = __half22float2(*(__half2*)&Gh[h][2]);
            float2 G1b = __half22float2(*(__half2*)&Gh[h][3]);
            A[h][0] = h16x2(o0[1]*inv0*G0a.y, o0[0]*inv0*G0a.x);
            A[h][1] = h16x2(o0[3]*inv1*G1a.y, o0[2]*inv1*G1a.x);
            A[h][2] = h16x2(o1[1]*inv0*G0b.y, o1[0]*inv0*G0b.x);
            A[h][3] = h16x2(o1[3]*inv1*G1b.y, o1[2]*inv1*G1b.x);
        }

        if (h < 3) __syncthreads();             // publish K/V head h+1
    }
#undef PROJ_JP

    // ---- fused output projection (Wo frags via ldmatrix) ----
    #pragma unroll
    for (int jp = 0; jp < 4; jp++) {
        float acc[2][4];
        #pragma unroll
        for (int jj = 0; jj < 2; jj++)
            #pragma unroll
            for (int k = 0; k < 4; k++) acc[jj][k] = 0.f;

        const uint32_t wbase = (jp*16 + frow)*144 + fcol;
        #pragma unroll
        for (int h = 0; h < 4; h++) {
            uint32_t wm[4];
            LDSM4(wm, sb + SM_WO + wbase + h*32);
            uint32_t b0[2] = {wm[0], wm[2]}, b1[2] = {wm[1], wm[3]};
            mma_f16(acc[0], A[h], b0);
            mma_f16(acc[1], A[h], b1);
        }
        #pragma unroll
        for (int jj = 0; jj < 2; jj++) {
            const int c = (jp*2 + jj)*8 + 2*t;
            float2 bo2 = *(const float2*)(bo + c);
            *(float2*)(y + (size_t)r0*64 + c)     = make_float2(acc[jj][0]+bo2.x, acc[jj][1]+bo2.y);
            *(float2*)(y + (size_t)(r0+8)*64 + c) = make_float2(acc[jj][2]+bo2.x, acc[jj][3]+bo2.y);
        }
    }
}

// ---------------------------------------------------------------------------
extern "C" void kernel_launch(void* const* d_in, const int* in_sizes, int n_in,
                              void* d_out, int out_size)
{
    (void)in_sizes; (void)n_in; (void)out_size;
    const float* z  = (const float*)d_in[0];
    const float* ls = (const float*)d_in[1];
    const float* lb = (const float*)d_in[2];
    const float* Wq = (const float*)d_in[3];
    const float* Wk = (const float*)d_in[4];
    const float* Wv = (const float*)d_in[5];
    const float* Wg = (const float*)d_in[6];
    const float* bg = (const float*)d_in[7];
    const float* Wo = (const float*)d_in[8];
    const float* bo = (const float*)d_in[9];
    float* y = (float*)d_out;

    (void)cudaFuncSetAttribute(k_fused, cudaFuncAttributeMaxDynamicSharedMemorySize, SMEMT);

    k_prep<<<32, 256>>>(Wq, Wk, Wv, Wg);
    k_fused<<<BATCH*LEN, 512, SMEMT>>>(z, ls, lb, bg, Wo, bo, y);
}